// round 8
// baseline (speedup 1.0000x reference)
#include <cuda_runtime.h>
#include <cuda_bf16.h>
#include <math.h>

#define CC   8
#define NN   16384
#define DD   1024
#define DQQ  128
#define KK   128
#define CAND_CAP 2048

static __device__ __align__(16) float g_w[CC * DD];
static __device__ float g_cc[CC];
static __device__ float g_scores[CC * NN];
static __device__ int   g_topidx[CC * KK];
static __device__ float g_weights[CC * KK];
static __device__ float g_u[CC * DD];
static __device__ float g_qk[CC * DQQ];
static __device__ unsigned int g_hist[CC * 2048];
static __device__ float g_esum[CC];

__device__ __forceinline__ unsigned int f2k(float f) {
    unsigned int u = __float_as_uint(f);
    return (u & 0x80000000u) ? ~u : (u | 0x80000000u);
}
__device__ __forceinline__ float k2f(unsigned int k) {
    unsigned int u = (k & 0x80000000u) ? (k & 0x7fffffffu) : ~k;
    return __uint_as_float(u);
}

// ---------------------------------------------------------------------------
// Kernel Z: zero scratch + init fusion output region to bv. grid 64 x 256
// ---------------------------------------------------------------------------
__global__ void zero_kernel(const float* __restrict__ bv, float* __restrict__ out) {
    const int idx = blockIdx.x * 256 + threadIdx.x;   // 0..16383
    g_hist[idx] = 0u;
    if (idx < CC * DD) {
        g_u[idx] = 0.f;
        out[(size_t)CC * KK * DD + idx] = bv[idx & (DD - 1)];
    }
    if (idx < CC * DQQ) g_qk[idx] = 0.f;
    if (idx < CC) g_esum[idx] = 0.f;
}

// ---------------------------------------------------------------------------
// Kernel A1: qk[c][j] = sum_i key[c][i] * Wq[i][j] + bq[j]  (via partials)
// grid (C, 8), block 128: block reduces a 128-row chunk of Wq.
// ---------------------------------------------------------------------------
__global__ void __launch_bounds__(128) qk_kernel(const float* __restrict__ key_feats,
                                                 const float* __restrict__ Wq,
                                                 const float* __restrict__ bq) {
    __shared__ float s_key[128];
    const int c  = blockIdx.x;
    const int ib = blockIdx.y * 128;
    const int j  = threadIdx.x;

    s_key[j] = key_feats[c * DD + ib + j];
    __syncthreads();

    float acc = (blockIdx.y == 0) ? bq[j] : 0.f;
    #pragma unroll 8
    for (int k = 0; k < 128; ++k)
        acc += s_key[k] * Wq[(size_t)(ib + k) * DQQ + j];
    atomicAdd(&g_qk[c * DQQ + j], acc);
}

// ---------------------------------------------------------------------------
// Kernel A2: w[c][i] = Wq[i] . qk[c]  (warp per row), cc = bq . qk
// grid (C, 8), block 128 (4 warps, 32 rows each)
// ---------------------------------------------------------------------------
__global__ void __launch_bounds__(128) w_kernel(const float* __restrict__ Wq,
                                                const float* __restrict__ bq) {
    __shared__ float s_qk[DQQ];
    const int c    = blockIdx.x;
    const int rb   = blockIdx.y * 128;
    const int t    = threadIdx.x;
    const int warp = t >> 5;
    const int lane = t & 31;

    s_qk[t] = g_qk[c * DQQ + t];
    __syncthreads();

    const float4 qk4 = reinterpret_cast<const float4*>(s_qk)[lane];

    if (blockIdx.y == 0 && warp == 0) {
        const float4 b4 = reinterpret_cast<const float4*>(bq)[lane];
        float cc = b4.x * qk4.x + b4.y * qk4.y + b4.z * qk4.z + b4.w * qk4.w;
        #pragma unroll
        for (int o = 16; o > 0; o >>= 1) cc += __shfl_xor_sync(0xffffffffu, cc, o);
        if (lane == 0) g_cc[c] = cc;
    }

    #pragma unroll 1
    for (int r = warp; r < 128; r += 4) {
        const int i = rb + r;
        const float4 w4 = reinterpret_cast<const float4*>(Wq + (size_t)i * DQQ)[lane];
        float acc = w4.x * qk4.x + w4.y * qk4.y + w4.z * qk4.z + w4.w * qk4.w;
        #pragma unroll
        for (int o = 16; o > 0; o >>= 1) acc += __shfl_xor_sync(0xffffffffu, acc, o);
        if (lane == 0) g_w[c * DD + i] = acc;
    }
}

// ---------------------------------------------------------------------------
// Kernel B: raw attention scores. Warp-per-row, streaming loads (__ldcs).
// Fused: lane 0 also bins the score into the global histogram and
// accumulates the softmax denominator (block-local, then one atomic).
// THE 512MB kernel. grid (256, C), block 256. 64 patches/block, 8/warp.
// ---------------------------------------------------------------------------
__global__ void __launch_bounds__(256) score_kernel(const float* __restrict__ feats) {
    __shared__ float s_esum;
    const int c    = blockIdx.y;
    const int warp = threadIdx.x >> 5;
    const int lane = threadIdx.x & 31;
    const float invSqDQ = 0.08838834764831843f;  // 1/sqrt(128)

    if (threadIdx.x == 0) s_esum = 0.f;

    float4 wreg[8];
    const float4* w4 = reinterpret_cast<const float4*>(g_w + c * DD);
    #pragma unroll
    for (int j = 0; j < 8; ++j) wreg[j] = w4[j * 32 + lane];
    const float cc = g_cc[c];
    __syncthreads();

    const int PPB  = 64;
    const int base = blockIdx.x * PPB;

    float esum = 0.f;
    #pragma unroll 1
    for (int p = warp; p < PPB; p += 8) {
        const int n = base + p;
        const float4* row = reinterpret_cast<const float4*>(
            feats + ((size_t)c * NN + n) * DD);
        float4 f0 = __ldcs(&row[0 * 32 + lane]);
        float4 f1 = __ldcs(&row[1 * 32 + lane]);
        float4 f2 = __ldcs(&row[2 * 32 + lane]);
        float4 f3 = __ldcs(&row[3 * 32 + lane]);
        float4 f4 = __ldcs(&row[4 * 32 + lane]);
        float4 f5 = __ldcs(&row[5 * 32 + lane]);
        float4 f6 = __ldcs(&row[6 * 32 + lane]);
        float4 f7 = __ldcs(&row[7 * 32 + lane]);

        float acc = f0.x * wreg[0].x + f0.y * wreg[0].y + f0.z * wreg[0].z + f0.w * wreg[0].w;
        acc += f1.x * wreg[1].x + f1.y * wreg[1].y + f1.z * wreg[1].z + f1.w * wreg[1].w;
        acc += f2.x * wreg[2].x + f2.y * wreg[2].y + f2.z * wreg[2].z + f2.w * wreg[2].w;
        acc += f3.x * wreg[3].x + f3.y * wreg[3].y + f3.z * wreg[3].z + f3.w * wreg[3].w;
        acc += f4.x * wreg[4].x + f4.y * wreg[4].y + f4.z * wreg[4].z + f4.w * wreg[4].w;
        acc += f5.x * wreg[5].x + f5.y * wreg[5].y + f5.z * wreg[5].z + f5.w * wreg[5].w;
        acc += f6.x * wreg[6].x + f6.y * wreg[6].y + f6.z * wreg[6].z + f6.w * wreg[6].w;
        acc += f7.x * wreg[7].x + f7.y * wreg[7].y + f7.z * wreg[7].z + f7.w * wreg[7].w;

        #pragma unroll
        for (int o = 16; o > 0; o >>= 1)
            acc += __shfl_xor_sync(0xffffffffu, acc, o);
        if (lane == 0) {
            float s = acc + cc;
            g_scores[c * NN + n] = s;
            esum += expf(s * invSqDQ);
            atomicAdd(&g_hist[c * 2048 + (f2k(s) >> 21)], 1u);
        }
    }
    if (lane == 0) atomicAdd(&s_esum, esum);
    __syncthreads();
    if (threadIdx.x == 0) atomicAdd(&g_esum[c], s_esum);
}

// ---------------------------------------------------------------------------
// Kernel C: per-cluster top-K (sorted desc, stable ties) + both softmaxes.
// grid: (C), block: 1024
// ---------------------------------------------------------------------------
__device__ __forceinline__ float blk_sum_f32(float v, float* red) {
    int t = threadIdx.x;
    red[t] = v; __syncthreads();
    for (int s = 512; s > 0; s >>= 1) {
        if (t < s) red[t] += red[t + s];
        __syncthreads();
    }
    float r = red[0];
    __syncthreads();
    return r;
}
__device__ __forceinline__ int blk_max_i32(int v, int* red) {
    int t = threadIdx.x;
    red[t] = v; __syncthreads();
    for (int s = 512; s > 0; s >>= 1) {
        if (t < s) { int o = red[t + s]; if (o > red[t]) red[t] = o; }
        __syncthreads();
    }
    int r = red[0];
    __syncthreads();
    return r;
}

__global__ void __launch_bounds__(1024) select_kernel() {
    __shared__ unsigned int       hist[2048];
    __shared__ unsigned long long cand[CAND_CAP];
    __shared__ float              redf[1024];
    __shared__ int                redi[1024];
    __shared__ unsigned long long red64[1024];
    __shared__ unsigned int       s_cnt;
    __shared__ float              s_p0;
    __shared__ unsigned long long s_prev;

    const int c = blockIdx.x;
    const int t = threadIdx.x;
    const float invSqDQ = 0.08838834764831843f;  // 1/sqrt(128)
    const float invSqD  = 0.03125f;              // 1/sqrt(1024)

    hist[t]        = g_hist[c * 2048 + t];
    hist[t + 1024] = g_hist[c * 2048 + t + 1024];
    if (t == 0) s_cnt = 0u;
    __syncthreads();

    // Suffix scan: hist[b] <- count of keys in buckets >= b (Hillis-Steele)
    #pragma unroll
    for (int s = 1; s < 2048; s <<= 1) {
        unsigned int a0 = hist[t]        + ((t + s < 2048)        ? hist[t + s]        : 0u);
        unsigned int a1 = hist[t + 1024] + ((t + 1024 + s < 2048) ? hist[t + 1024 + s] : 0u);
        __syncthreads();
        hist[t] = a0; hist[t + 1024] = a1;
        __syncthreads();
    }

    // B = largest bucket with suffix count >= K
    int loc = -1;
    if (hist[t + 1024] >= KK) loc = t + 1024;
    else if (hist[t] >= KK)   loc = t;
    const int B = blk_max_i32(loc, redi);
    __syncthreads();

    // Collect candidates (L2-resident scores)
    for (int i = t; i < NN; i += 1024) {
        unsigned int key = f2k(g_scores[c * NN + i]);
        if ((int)(key >> 21) >= B) {
            unsigned int pos = atomicAdd(&s_cnt, 1u);
            if (pos < CAND_CAP)
                cand[pos] = ((unsigned long long)key << 14) |
                            (unsigned long long)(16383 - i);  // tie: lower idx wins
        }
    }
    __syncthreads();
    const unsigned int M = s_cnt;

    if (M <= CAND_CAP) {
        int P = 128;
        while (P < (int)M) P <<= 1;
        for (int i = (int)M + t; i < P; i += 1024) cand[i] = 0ull;
        __syncthreads();
        for (int k = 2; k <= P; k <<= 1) {
            for (int j = k >> 1; j > 0; j >>= 1) {
                for (int i = t; i < P; i += 1024) {
                    int ixj = i ^ j;
                    if (ixj > i) {
                        unsigned long long a = cand[i], b = cand[ixj];
                        bool swap_ = ((i & k) == 0) ? (a < b) : (a > b);
                        if (swap_) { cand[i] = b; cand[ixj] = a; }
                    }
                }
                __syncthreads();
            }
        }
    } else {
        // Degenerate-ties fallback: K sequential arg-maxes (exact; never hit on
        // continuous data)
        if (t == 0) s_prev = 0xFFFFFFFFFFFFFFFFull;
        __syncthreads();
        for (int kk = 0; kk < KK; ++kk) {
            unsigned long long prev = s_prev;
            unsigned long long local = 0ull;
            for (int i = t; i < NN; i += 1024) {
                unsigned int key = f2k(g_scores[c * NN + i]);
                unsigned long long v = ((unsigned long long)key << 14) |
                                       (unsigned long long)(16383 - i);
                if (v < prev && v > local) local = v;
            }
            red64[t] = local; __syncthreads();
            for (int s = 512; s > 0; s >>= 1) {
                if (t < s) { unsigned long long o = red64[t + s]; if (o > red64[t]) red64[t] = o; }
                __syncthreads();
            }
            if (t == 0) { cand[kk] = red64[0]; s_prev = red64[0]; }
            __syncthreads();
        }
    }

    // Top-128: first-softmax probs, then re-softmax over top-K
    float p = 0.f;
    if (t < KK) {
        unsigned long long v = cand[t];
        int idx = 16383 - (int)(v & 0x3FFFull);
        float f = k2f((unsigned int)(v >> 14));
        p = expf(f * invSqDQ) / g_esum[c];
        g_topidx[c * KK + t] = idx;
        if (t == 0) s_p0 = p;   // cand sorted desc -> t==0 is max prob
    }
    __syncthreads();
    float e = (t < KK) ? expf((p - s_p0) * invSqD) : 0.f;
    float wsum = blk_sum_f32(e, redf);
    if (t < KK) g_weights[c * KK + t] = e / wsum;
}

// ---------------------------------------------------------------------------
// Kernel D: gather selected rows to output + partial weighted sums into g_u.
// grid (C, 32), block 256 (thread = one float4 column; 4 rows per block)
// ---------------------------------------------------------------------------
__global__ void __launch_bounds__(256) gather_kernel(const float* __restrict__ feats,
                                                     float* __restrict__ out) {
    __shared__ float sw[4];
    __shared__ int   sidx[4];
    const int c  = blockIdx.x;
    const int ks = blockIdx.y * 4;
    const int t  = threadIdx.x;
    if (t < 4) {
        sw[t]   = g_weights[c * KK + ks + t];
        sidx[t] = g_topidx[c * KK + ks + t];
    }
    __syncthreads();

    float4 acc = make_float4(0.f, 0.f, 0.f, 0.f);
    #pragma unroll
    for (int r = 0; r < 4; ++r) {
        const float4* row = reinterpret_cast<const float4*>(
            feats + ((size_t)c * NN + sidx[r]) * DD);
        float4 v = row[t];
        reinterpret_cast<float4*>(out + ((size_t)(c * KK + ks + r)) * DD)[t] = v;
        float w = sw[r];
        acc.x += w * v.x; acc.y += w * v.y; acc.z += w * v.z; acc.w += w * v.w;
    }
    float* u = g_u + c * DD + t * 4;
    atomicAdd(u + 0, acc.x);
    atomicAdd(u + 1, acc.y);
    atomicAdd(u + 2, acc.z);
    atomicAdd(u + 3, acc.w);
}

// ---------------------------------------------------------------------------
// Kernel E: fusion_c += u_c @ Wv (bv pre-initialized by zero_kernel)
// grid (C, 8 colsegs, 4 isegs), block 128
// ---------------------------------------------------------------------------
__global__ void __launch_bounds__(128) fusion_kernel(const float* __restrict__ Wv,
                                                     float* __restrict__ out) {
    __shared__ float su[256];
    const int c  = blockIdx.x;
    const int t  = threadIdx.x;
    const int i0 = blockIdx.z * 256;
    su[t]       = g_u[c * DD + i0 + t];
    su[t + 128] = g_u[c * DD + i0 + t + 128];
    __syncthreads();

    const int j = blockIdx.y * 128 + t;
    float acc = 0.f;
    #pragma unroll 8
    for (int i = 0; i < 256; ++i) acc += su[i] * Wv[(size_t)(i0 + i) * DD + j];
    atomicAdd(&out[(size_t)CC * KK * DD + (size_t)c * DD + j], acc);
}

// ---------------------------------------------------------------------------
extern "C" void kernel_launch(void* const* d_in, const int* in_sizes, int n_in,
                              void* d_out, int out_size) {
    const float* feats = (const float*)d_in[0];  // [C, N, D]
    const float* keyf  = (const float*)d_in[1];  // [C, 1, D]
    const float* Wq    = (const float*)d_in[2];  // [D, DQ]
    const float* bq    = (const float*)d_in[3];  // [DQ]
    const float* Wv    = (const float*)d_in[4];  // [D, D]
    const float* bv    = (const float*)d_in[5];  // [D]
    float* out = (float*)d_out;                  // [C*K*D | C*D]

    zero_kernel<<<64, 256>>>(bv, out);
    qk_kernel<<<dim3(CC, 8), 128>>>(keyf, Wq, bq);
    w_kernel<<<dim3(CC, 8), 128>>>(Wq, bq);
    score_kernel<<<dim3(256, CC), 256>>>(feats);
    select_kernel<<<CC, 1024>>>();
    gather_kernel<<<dim3(CC, 32), 256>>>(feats, out);
    fusion_kernel<<<dim3(CC, 8, 4), 128>>>(Wv, out);
}

// round 11
// speedup vs baseline: 1.0492x; 1.0492x over previous
#include <cuda_runtime.h>
#include <cuda_bf16.h>
#include <math.h>

#define CC   8
#define NN   16384
#define DD   1024
#define DQQ  128
#define KK   128
#define CAND_CAP 2048

static __device__ __align__(16) float g_w[CC * DD];
static __device__ float g_cc[CC];
static __device__ float g_scores[CC * NN];
static __device__ int   g_topidx[CC * KK];
static __device__ float g_weights[CC * KK];
static __device__ float g_u[CC * DD];                 // zeroed by select each launch
static __device__ float g_qkp[CC * 8 * DQQ];          // partials, overwritten each launch
static __device__ unsigned int g_hist[CC * 2048];     // zero-at-start invariant (select restores)
static __device__ float g_esum[CC];                   // zero-at-start invariant (select restores)

__device__ __forceinline__ unsigned int f2k(float f) {
    unsigned int u = __float_as_uint(f);
    return (u & 0x80000000u) ? ~u : (u | 0x80000000u);
}
__device__ __forceinline__ float k2f(unsigned int k) {
    unsigned int u = (k & 0x80000000u) ? (k & 0x7fffffffu) : ~k;
    return __uint_as_float(u);
}

// ---------------------------------------------------------------------------
// Kernel A1: qk partials: g_qkp[c][y][j] = sum_{i in chunk y} key[c][i]*Wq[i][j]
// grid (C, 8), block 128. No atomics -> no pre-zero needed.
// ---------------------------------------------------------------------------
__global__ void __launch_bounds__(128) qk_kernel(const float* __restrict__ key_feats,
                                                 const float* __restrict__ Wq) {
    __shared__ float s_key[128];
    const int c  = blockIdx.x;
    const int ib = blockIdx.y * 128;
    const int j  = threadIdx.x;

    s_key[j] = key_feats[c * DD + ib + j];
    __syncthreads();

    float acc = 0.f;
    #pragma unroll 8
    for (int k = 0; k < 128; ++k)
        acc += s_key[k] * Wq[(size_t)(ib + k) * DQQ + j];
    g_qkp[(c * 8 + blockIdx.y) * DQQ + j] = acc;
}

// ---------------------------------------------------------------------------
// Kernel A2: qk = bq + sum of partials; w[c][i] = Wq[i] . qk; cc = bq . qk
// grid (C, 8), block 128 (4 warps, 32 rows each)
// ---------------------------------------------------------------------------
__global__ void __launch_bounds__(128) w_kernel(const float* __restrict__ Wq,
                                                const float* __restrict__ bq) {
    __shared__ float s_qk[DQQ];
    const int c    = blockIdx.x;
    const int rb   = blockIdx.y * 128;
    const int t    = threadIdx.x;
    const int warp = t >> 5;
    const int lane = t & 31;

    float q = bq[t];
    #pragma unroll
    for (int y = 0; y < 8; ++y) q += g_qkp[(c * 8 + y) * DQQ + t];
    s_qk[t] = q;
    __syncthreads();

    const float4 qk4 = reinterpret_cast<const float4*>(s_qk)[lane];

    if (blockIdx.y == 0 && warp == 0) {
        const float4 b4 = reinterpret_cast<const float4*>(bq)[lane];
        float cc = b4.x * qk4.x + b4.y * qk4.y + b4.z * qk4.z + b4.w * qk4.w;
        #pragma unroll
        for (int o = 16; o > 0; o >>= 1) cc += __shfl_xor_sync(0xffffffffu, cc, o);
        if (lane == 0) g_cc[c] = cc;
    }

    #pragma unroll 1
    for (int r = warp; r < 128; r += 4) {
        const int i = rb + r;
        const float4 w4 = reinterpret_cast<const float4*>(Wq + (size_t)i * DQQ)[lane];
        float acc = w4.x * qk4.x + w4.y * qk4.y + w4.z * qk4.z + w4.w * qk4.w;
        #pragma unroll
        for (int o = 16; o > 0; o >>= 1) acc += __shfl_xor_sync(0xffffffffu, acc, o);
        if (lane == 0) g_w[c * DD + i] = acc;
    }
}

// ---------------------------------------------------------------------------
// Kernel B: raw attention scores. Warp-per-row, streaming loads (__ldcs).
// Fused: lane 0 bins into global histogram + accumulates softmax denominator.
// THE 512MB kernel. grid (256, C), block 256. (unchanged from 131us champion)
// ---------------------------------------------------------------------------
__global__ void __launch_bounds__(256) score_kernel(const float* __restrict__ feats) {
    __shared__ float s_esum;
    const int c    = blockIdx.y;
    const int warp = threadIdx.x >> 5;
    const int lane = threadIdx.x & 31;
    const float invSqDQ = 0.08838834764831843f;  // 1/sqrt(128)

    if (threadIdx.x == 0) s_esum = 0.f;

    float4 wreg[8];
    const float4* w4 = reinterpret_cast<const float4*>(g_w + c * DD);
    #pragma unroll
    for (int j = 0; j < 8; ++j) wreg[j] = w4[j * 32 + lane];
    const float cc = g_cc[c];
    __syncthreads();

    const int PPB  = 64;
    const int base = blockIdx.x * PPB;

    float esum = 0.f;
    #pragma unroll 1
    for (int p = warp; p < PPB; p += 8) {
        const int n = base + p;
        const float4* row = reinterpret_cast<const float4*>(
            feats + ((size_t)c * NN + n) * DD);
        float4 f0 = __ldcs(&row[0 * 32 + lane]);
        float4 f1 = __ldcs(&row[1 * 32 + lane]);
        float4 f2 = __ldcs(&row[2 * 32 + lane]);
        float4 f3 = __ldcs(&row[3 * 32 + lane]);
        float4 f4 = __ldcs(&row[4 * 32 + lane]);
        float4 f5 = __ldcs(&row[5 * 32 + lane]);
        float4 f6 = __ldcs(&row[6 * 32 + lane]);
        float4 f7 = __ldcs(&row[7 * 32 + lane]);

        float acc = f0.x * wreg[0].x + f0.y * wreg[0].y + f0.z * wreg[0].z + f0.w * wreg[0].w;
        acc += f1.x * wreg[1].x + f1.y * wreg[1].y + f1.z * wreg[1].z + f1.w * wreg[1].w;
        acc += f2.x * wreg[2].x + f2.y * wreg[2].y + f2.z * wreg[2].z + f2.w * wreg[2].w;
        acc += f3.x * wreg[3].x + f3.y * wreg[3].y + f3.z * wreg[3].z + f3.w * wreg[3].w;
        acc += f4.x * wreg[4].x + f4.y * wreg[4].y + f4.z * wreg[4].z + f4.w * wreg[4].w;
        acc += f5.x * wreg[5].x + f5.y * wreg[5].y + f5.z * wreg[5].z + f5.w * wreg[5].w;
        acc += f6.x * wreg[6].x + f6.y * wreg[6].y + f6.z * wreg[6].z + f6.w * wreg[6].w;
        acc += f7.x * wreg[7].x + f7.y * wreg[7].y + f7.z * wreg[7].z + f7.w * wreg[7].w;

        #pragma unroll
        for (int o = 16; o > 0; o >>= 1)
            acc += __shfl_xor_sync(0xffffffffu, acc, o);
        if (lane == 0) {
            float s = acc + cc;
            g_scores[c * NN + n] = s;
            esum += expf(s * invSqDQ);
            atomicAdd(&g_hist[c * 2048 + (f2k(s) >> 21)], 1u);
        }
    }
    if (lane == 0) atomicAdd(&s_esum, esum);
    __syncthreads();
    if (threadIdx.x == 0) atomicAdd(&g_esum[c], s_esum);
}

// ---------------------------------------------------------------------------
// Kernel C: per-cluster top-K (sorted desc, stable ties) + both softmaxes.
// Also: restores g_hist/g_esum to zero (graph-replay invariant), zeroes g_u,
// writes bv into the fusion output region. Rank-based ordering (O(M^2), one
// barrier) replaces the bitonic sort. grid: (C), block: 1024
// ---------------------------------------------------------------------------
__device__ __forceinline__ float blk_sum_f32(float v, float* red) {
    int t = threadIdx.x;
    red[t] = v; __syncthreads();
    for (int s = 512; s > 0; s >>= 1) {
        if (t < s) red[t] += red[t + s];
        __syncthreads();
    }
    float r = red[0];
    __syncthreads();
    return r;
}
__device__ __forceinline__ int blk_max_i32(int v, int* red) {
    int t = threadIdx.x;
    red[t] = v; __syncthreads();
    for (int s = 512; s > 0; s >>= 1) {
        if (t < s) { int o = red[t + s]; if (o > red[t]) red[t] = o; }
        __syncthreads();
    }
    int r = red[0];
    __syncthreads();
    return r;
}

__global__ void __launch_bounds__(1024) select_kernel(const float* __restrict__ bv,
                                                      float* __restrict__ out) {
    __shared__ unsigned int       hist[2048];
    __shared__ unsigned long long cand[CAND_CAP];
    __shared__ float              redf[1024];
    __shared__ int                redi[1024];
    __shared__ unsigned long long red64[1024];
    __shared__ unsigned int       s_cnt;
    __shared__ float              s_esum, s_p0;
    __shared__ unsigned long long s_prev;
    __shared__ float              pbuf[KK];

    const int c = blockIdx.x;
    const int t = threadIdx.x;
    const float invSqDQ = 0.08838834764831843f;  // 1/sqrt(128)
    const float invSqD  = 0.03125f;              // 1/sqrt(1024)

    // load + restore-to-zero the global hist / esum; zero g_u; init out with bv
    hist[t]        = g_hist[c * 2048 + t];
    hist[t + 1024] = g_hist[c * 2048 + t + 1024];
    g_hist[c * 2048 + t] = 0u;
    g_hist[c * 2048 + t + 1024] = 0u;
    g_u[c * DD + t] = 0.f;
    out[(size_t)CC * KK * DD + (size_t)c * DD + t] = bv[t];
    if (t == 0) {
        s_cnt = 0u;
        s_esum = g_esum[c];
        g_esum[c] = 0.f;
    }
    __syncthreads();

    // Suffix scan: hist[b] <- count of keys in buckets >= b (Hillis-Steele)
    #pragma unroll
    for (int s = 1; s < 2048; s <<= 1) {
        unsigned int a0 = hist[t]        + ((t + s < 2048)        ? hist[t + s]        : 0u);
        unsigned int a1 = hist[t + 1024] + ((t + 1024 + s < 2048) ? hist[t + 1024 + s] : 0u);
        __syncthreads();
        hist[t] = a0; hist[t + 1024] = a1;
        __syncthreads();
    }

    // B = largest bucket with suffix count >= K
    int loc = -1;
    if (hist[t + 1024] >= KK) loc = t + 1024;
    else if (hist[t] >= KK)   loc = t;
    const int B = blk_max_i32(loc, redi);
    __syncthreads();

    // Collect candidates (L2-resident scores)
    for (int i = t; i < NN; i += 1024) {
        unsigned int key = f2k(g_scores[c * NN + i]);
        if ((int)(key >> 21) >= B) {
            unsigned int pos = atomicAdd(&s_cnt, 1u);
            if (pos < CAND_CAP)
                cand[pos] = ((unsigned long long)key << 14) |
                            (unsigned long long)(16383 - i);  // tie: lower idx wins
        }
    }
    __syncthreads();
    const unsigned int M = s_cnt;
    const float esum = s_esum;

    if (M <= CAND_CAP) {
        // Rank-based top-K: keys are unique, rank = #greater keys = output slot
        for (int i = t; i < (int)M; i += 1024) {
            unsigned long long a = cand[i];
            int rank = 0;
            for (int j = 0; j < (int)M; ++j) rank += (cand[j] > a);
            if (rank < KK) {
                int idx = 16383 - (int)(a & 0x3FFFull);
                float f = k2f((unsigned int)(a >> 14));
                g_topidx[c * KK + rank] = idx;
                pbuf[rank] = expf(f * invSqDQ) / esum;
            }
        }
        __syncthreads();
    } else {
        // Degenerate-ties fallback: K sequential arg-maxes (exact; never hit on
        // continuous data)
        if (t == 0) s_prev = 0xFFFFFFFFFFFFFFFFull;
        __syncthreads();
        for (int kk = 0; kk < KK; ++kk) {
            unsigned long long prev = s_prev;
            unsigned long long local = 0ull;
            for (int i = t; i < NN; i += 1024) {
                unsigned int key = f2k(g_scores[c * NN + i]);
                unsigned long long v = ((unsigned long long)key << 14) |
                                       (unsigned long long)(16383 - i);
                if (v < prev && v > local) local = v;
            }
            red64[t] = local; __syncthreads();
            for (int s = 512; s > 0; s >>= 1) {
                if (t < s) { unsigned long long o = red64[t + s]; if (o > red64[t]) red64[t] = o; }
                __syncthreads();
            }
            if (t == 0) { s_prev = red64[0]; }
            __syncthreads();
            if (t == 0) {
                unsigned long long v = s_prev;
                int idx = 16383 - (int)(v & 0x3FFFull);
                float f = k2f((unsigned int)(v >> 14));
                g_topidx[c * KK + kk] = idx;
                pbuf[kk] = expf(f * invSqDQ) / esum;
            }
            __syncthreads();
        }
    }

    // Second softmax over the K first-softmax probabilities
    if (t == 0) s_p0 = pbuf[0];   // rank 0 = max prob
    __syncthreads();
    float p = (t < KK) ? pbuf[t] : 0.f;
    float e = (t < KK) ? expf((p - s_p0) * invSqD) : 0.f;
    float wsum = blk_sum_f32(e, redf);
    if (t < KK) g_weights[c * KK + t] = e / wsum;
}

// ---------------------------------------------------------------------------
// Kernel D: gather selected rows to output + partial weighted sums into g_u
// (g_u zeroed by select). grid (C, 32), block 256 (thread = one float4 col)
// ---------------------------------------------------------------------------
__global__ void __launch_bounds__(256) gather_kernel(const float* __restrict__ feats,
                                                     float* __restrict__ out) {
    __shared__ float sw[4];
    __shared__ int   sidx[4];
    const int c  = blockIdx.x;
    const int ks = blockIdx.y * 4;
    const int t  = threadIdx.x;
    if (t < 4) {
        sw[t]   = g_weights[c * KK + ks + t];
        sidx[t] = g_topidx[c * KK + ks + t];
    }
    __syncthreads();

    float4 acc = make_float4(0.f, 0.f, 0.f, 0.f);
    #pragma unroll
    for (int r = 0; r < 4; ++r) {
        const float4* row = reinterpret_cast<const float4*>(
            feats + ((size_t)c * NN + sidx[r]) * DD);
        float4 v = row[t];
        reinterpret_cast<float4*>(out + ((size_t)(c * KK + ks + r)) * DD)[t] = v;
        float w = sw[r];
        acc.x += w * v.x; acc.y += w * v.y; acc.z += w * v.z; acc.w += w * v.w;
    }
    float* u = g_u + c * DD + t * 4;
    atomicAdd(u + 0, acc.x);
    atomicAdd(u + 1, acc.y);
    atomicAdd(u + 2, acc.z);
    atomicAdd(u + 3, acc.w);
}

// ---------------------------------------------------------------------------
// Kernel E: fusion_c += u_c @ Wv (bv pre-initialized by select_kernel)
// grid (C, 8 colsegs, 4 isegs), block 128
// ---------------------------------------------------------------------------
__global__ void __launch_bounds__(128) fusion_kernel(const float* __restrict__ Wv,
                                                     float* __restrict__ out) {
    __shared__ float su[256];
    const int c  = blockIdx.x;
    const int t  = threadIdx.x;
    const int i0 = blockIdx.z * 256;
    su[t]       = g_u[c * DD + i0 + t];
    su[t + 128] = g_u[c * DD + i0 + t + 128];
    __syncthreads();

    const int j = blockIdx.y * 128 + t;
    float acc = 0.f;
    #pragma unroll 8
    for (int i = 0; i < 256; ++i) acc += su[i] * Wv[(size_t)(i0 + i) * DD + j];
    atomicAdd(&out[(size_t)CC * KK * DD + (size_t)c * DD + j], acc);
}

// ---------------------------------------------------------------------------
extern "C" void kernel_launch(void* const* d_in, const int* in_sizes, int n_in,
                              void* d_out, int out_size) {
    const float* feats = (const float*)d_in[0];  // [C, N, D]
    const float* keyf  = (const float*)d_in[1];  // [C, 1, D]
    const float* Wq    = (const float*)d_in[2];  // [D, DQ]
    const float* bq    = (const float*)d_in[3];  // [DQ]
    const float* Wv    = (const float*)d_in[4];  // [D, D]
    const float* bv    = (const float*)d_in[5];  // [D]
    float* out = (float*)d_out;                  // [C*K*D | C*D]

    qk_kernel<<<dim3(CC, 8), 128>>>(keyf, Wq);
    w_kernel<<<dim3(CC, 8), 128>>>(Wq, bq);
    score_kernel<<<dim3(256, CC), 256>>>(feats);
    select_kernel<<<CC, 1024>>>(bv, out);
    gather_kernel<<<dim3(CC, 32), 256>>>(feats, out);
    fusion_kernel<<<dim3(CC, 8, 4), 128>>>(Wv, out);
}